// round 15
// baseline (speedup 1.0000x reference)
#include <cuda_runtime.h>
#include <cuda_fp16.h>
#include <cstdint>
#include <cstddef>

#define B_ 2
#define C_ 256
#define N_ 4096
#define CN (C_*N_)

typedef __half hf;

// ---------------- scratch (static __device__, no allocation) ----------------
__device__ float g_partial[B_*N_*32];  // per (b,i,mtile128) partial exp-sums
__device__ float g_rinv[B_*N_];        // 1/rowsum

// fp16 hi/lo split operands
__device__ hf g_hnTh[B_*N_*C_], g_hnTl[B_*N_*C_]; // hn^T (b, n, c)
__device__ hf g_w4h[4*C_*C_],   g_w4l[4*C_*C_];   // wq, wk, wv, wp (o, c)
__device__ hf g_qT [B_*N_*C_];                    // qT (b, n, c) SINGLE fp16
__device__ hf g_kTh[B_*N_*C_],  g_kTl[B_*N_*C_];  // kT (b, n, c)
__device__ hf g_vh [B_*CN],     g_vl [B_*CN];     // v  (b, c, n)
__device__ hf g_hvTh[B_*N_*C_], g_hvTl[B_*N_*C_]; // hv^T (b, n, c)
__device__ hf g_eh [(size_t)B_*N_*N_];            // e (b, i, m) hi
__device__ hf g_el [(size_t)B_*N_*N_];            // e (b, i, m) lo

// ---------------- helpers ----------------
__device__ __forceinline__ uint32_t smem_u32(const void* p){
    uint32_t a;
    asm("{ .reg .u64 t; cvta.to.shared.u64 t, %1; cvt.u32.u64 %0, t; }" : "=r"(a) : "l"(p));
    return a;
}
__device__ __forceinline__ uint32_t sw128(uint32_t o){ return o ^ ((o >> 3) & 0x70); }

__device__ __forceinline__ void ldsm4(uint32_t r[4], uint32_t addr){
    asm volatile("ldmatrix.sync.aligned.m8n8.x4.shared.b16 {%0,%1,%2,%3}, [%4];"
        : "=r"(r[0]), "=r"(r[1]), "=r"(r[2]), "=r"(r[3]) : "r"(addr));
}
__device__ __forceinline__ void mma16816(float d[4], const uint32_t a[4], uint32_t b0, uint32_t b1){
    asm volatile("mma.sync.aligned.m16n8k16.row.col.f32.f16.f16.f32 "
        "{%0,%1,%2,%3}, {%4,%5,%6,%7}, {%8,%9}, {%0,%1,%2,%3};"
        : "+f"(d[0]), "+f"(d[1]), "+f"(d[2]), "+f"(d[3])
        : "r"(a[0]), "r"(a[1]), "r"(a[2]), "r"(a[3]), "r"(b0), "r"(b1));
}
__device__ __forceinline__ void cpa16(uint32_t dst, const void* src){
    asm volatile("cp.async.cg.shared.global [%0], [%1], 16;"
        :: "r"(dst), "l"(__cvta_generic_to_global(src)) : "memory");
}
#define CP_COMMIT() asm volatile("cp.async.commit_group;" ::: "memory")
#define CP_WAIT1()  asm volatile("cp.async.wait_group 1;" ::: "memory")
#define CP_WAIT0()  asm volatile("cp.async.wait_group 0;" ::: "memory")

__device__ __forceinline__ void hsplit2(float v0, float v1, uint32_t& hi, uint32_t& lo){
    hf h0 = __float2half(v0);
    hf h1 = __float2half(v1);
    hf l0 = __float2half(v0 - __half2float(h0));
    hf l1 = __float2half(v1 - __half2float(h1));
    hi = (uint32_t)__half_as_ushort(h0) | ((uint32_t)__half_as_ushort(h1) << 16);
    lo = (uint32_t)__half_as_ushort(l0) | ((uint32_t)__half_as_ushort(l1) << 16);
}

// ---------------- templated 2-stage 128xBN mma core ----------------
// A: 128 rows k-major (hi, + lo if AHL); B: BN rows k-major (hi+lo).
// Terms per k16: ah*bh + ah*bl (+ al*bh if AHL).
// Stage: AH@0 (16KB), [AL@16K], BH, BL (BN*128B each).
template<int BN, int AHL>
__device__ __forceinline__ void mc_load(
    const hf* __restrict__ Ah, const hf* __restrict__ Al,
    const hf* __restrict__ Bh, const hf* __restrict__ Bl,
    int stride, int kk, uint32_t sbuf)
{
    constexpr int BH_OFF = AHL ? 32768 : 16384;
    constexpr int BL_OFF = BH_OFF + BN*128;
    const int tid = threadIdx.x;
    #pragma unroll
    for (int t = 0; t < 4; t++){
        int idx = tid + t*256;
        int r = idx >> 3, c16 = idx & 7;
        uint32_t so = sw128((uint32_t)(r*128 + c16*16));
        size_t go = (size_t)r*stride + kk + c16*8;
        cpa16(sbuf + so, Ah + go);
        if (AHL) cpa16(sbuf + 16384 + so, Al + go);
    }
    #pragma unroll
    for (int t = 0; t < BN/32; t++){
        int idx = tid + t*256;
        int r = idx >> 3, c16 = idx & 7;
        uint32_t so = sw128((uint32_t)(r*128 + c16*16));
        size_t go = (size_t)r*stride + kk + c16*8;
        cpa16(sbuf + BH_OFF + so, Bh + go);
        cpa16(sbuf + BL_OFF + so, Bl + go);
    }
}

template<int BN, int AHL>
__device__ __forceinline__ void mc_compute(uint32_t sbuf, float acc[2][BN/16][4])
{
    constexpr int BH_OFF = AHL ? 32768 : 16384;
    constexpr int BL_OFF = BH_OFF + BN*128;
    const int tid  = threadIdx.x;
    const int lane = tid & 31, wid = tid >> 5;
    const int wm = (wid & 3) * 32, wn = (wid >> 2) * (BN/2);
    const int lrow = ((lane >> 3) & 1) * 8 + (lane & 7);
    const int lk   = (lane >> 4) * 8;
    #pragma unroll
    for (int k16 = 0; k16 < 4; k16++){
        uint32_t ah[2][4], al[2][4];
        #pragma unroll
        for (int mf = 0; mf < 2; mf++){
            uint32_t off = sw128((uint32_t)((wm + mf*16 + lrow)*128 + (k16*16 + lk)*2));
            ldsm4(ah[mf], sbuf + off);
            if (AHL) ldsm4(al[mf], sbuf + 16384 + off);
        }
        #pragma unroll
        for (int nf2 = 0; nf2 < BN/32; nf2++){
            uint32_t boff = sw128((uint32_t)((wn + nf2*16 + lrow)*128 + (k16*16 + lk)*2));
            uint32_t bh[4], bl[4];
            ldsm4(bh, sbuf + BH_OFF + boff);
            ldsm4(bl, sbuf + BL_OFF + boff);
            #pragma unroll
            for (int mf = 0; mf < 2; mf++){
                #pragma unroll
                for (int w = 0; w < 2; w++){
                    int nf = nf2*2 + w;
                    mma16816(acc[mf][nf], ah[mf], bh[w], bh[w+2]);
                    mma16816(acc[mf][nf], ah[mf], bl[w], bl[w+2]);
                    if (AHL) mma16816(acc[mf][nf], al[mf], bh[w], bh[w+2]);
                }
            }
        }
    }
}

template<int BN, int AHL>
__device__ __forceinline__ void mma_core(
    const hf* __restrict__ Ah, const hf* __restrict__ Al,
    const hf* __restrict__ Bh, const hf* __restrict__ Bl,
    int stride, int K, uint32_t sb, float acc[2][BN/16][4])
{
    constexpr int STAGE = (AHL ? 32768 : 16384) + BN*256;
    const int nch = K >> 6;
    mc_load<BN,AHL>(Ah, Al, Bh, Bl, stride, 0, sb);
    CP_COMMIT();
    for (int c = 0; c < nch; c++){
        if (c + 1 < nch){
            mc_load<BN,AHL>(Ah, Al, Bh, Bl, stride, (c+1)*64, sb + ((c+1)&1)*STAGE);
            CP_COMMIT();
            CP_WAIT1();
        } else {
            CP_WAIT0();
        }
        __syncthreads();
        mc_compute<BN,AHL>(sb + (c&1)*STAGE, acc);
        __syncthreads();
    }
}

#define SMEM_FULL (2*65536)    // BN=128, AHL=1 (qkv, proj): 1 CTA/SM
#define SMEM_SC   (2*49152)    // scores BN=128 AHL=0 / pv BN=64 AHL=1: 2 CTAs/SM

// ---------------- wq/wk/wv/wp -> fp16 hi/lo (layout unchanged: (o, c) k-major) ----------------
__global__ void conv_w4(const float* __restrict__ wq, const float* __restrict__ wk,
                        const float* __restrict__ wv, const float* __restrict__ wp){
    int idx = blockIdx.x*256 + threadIdx.x;       // 0 .. 4*32768-1 (pairs)
    int which = idx >> 15;
    int pair  = idx & 32767;
    const float* src = (which==0)?wq:(which==1)?wk:(which==2)?wv:wp;
    float v0 = src[pair*2], v1 = src[pair*2+1];
    uint32_t hi, lo;
    hsplit2(v0, v1, hi, lo);
    *(uint32_t*)&g_w4h[(size_t)which*C_*C_ + pair*2] = hi;
    *(uint32_t*)&g_w4l[(size_t)which*C_*C_ + pair*2] = lo;
}

// ---------------- GroupNorm -> hn^T (b, n, c) fp16 hi/lo ----------------
__global__ void gn_kernel(const float* __restrict__ x, const float* __restrict__ gma,
                          const float* __restrict__ bta){
    const int bg = blockIdx.x;                 // 64 = b*32 + grp
    const int b = bg >> 5, grp = bg & 31;
    const size_t base = (size_t)b*CN + (size_t)grp*8*N_;
    const float* xp = x + base;
    const int tid = threadIdx.x;
    float s = 0.f, sq = 0.f;
    for (int i = tid; i < 8*N_; i += 256){ float v = xp[i]; s += v; sq += v*v; }
    __shared__ float ss[256], sk[256];
    ss[tid]=s; sk[tid]=sq; __syncthreads();
    for (int o=128;o>0;o>>=1){
        if (tid < o){ ss[tid]+=ss[tid+o]; sk[tid]+=sk[tid+o]; }
        __syncthreads();
    }
    const float inv = 1.0f/(8.0f*N_);
    float mu = ss[0]*inv;
    float var = sk[0]*inv - mu*mu;
    float rs = rsqrtf(var + 1e-6f);
    float gm[8], bt[8];
    #pragma unroll
    for (int ch=0; ch<8; ch++){ gm[ch] = gma[grp*8+ch]*rs; bt[ch] = bta[grp*8+ch]; }
    for (int n = tid; n < N_; n += 256){
        uint32_t hi[4], lo[4];
        #pragma unroll
        for (int p=0; p<4; p++){
            float v0 = (xp[(size_t)(p*2  )*N_ + n] - mu)*gm[p*2]   + bt[p*2];
            float v1 = (xp[(size_t)(p*2+1)*N_ + n] - mu)*gm[p*2+1] + bt[p*2+1];
            hsplit2(v0, v1, hi[p], lo[p]);
        }
        size_t off = ((size_t)b*N_ + n)*C_ + grp*8;
        *(uint4*)&g_hnTh[off] = *(uint4*)hi;
        *(uint4*)&g_hnTl[off] = *(uint4*)lo;
    }
}

// ---------------- merged QKV: grid (2, 32, 6), z = which*2 + b ----------------
// which 0/1 (q/k): C[m=n][n=o] = sum_c hnT[n][c] w[o][c] + b[o]  -> qT single / kT hi,lo
// which 2   (v):   C[m=o][n=n] = sum_c w[o][c] hnT[n][c] + b[o]  -> v hi,lo (b,c,n)
__global__ void __launch_bounds__(256) qkv_mma(
    const float* __restrict__ bq, const float* __restrict__ bk, const float* __restrict__ bv)
{
    extern __shared__ char smem[];
    uint32_t sb = smem_u32(smem);
    const int z = blockIdx.z;
    const int which = z >> 1, b = z & 1;

    const hf *Ah, *Al, *Bh, *Bl;
    int m0, n0;
    if (which < 2){
        m0 = blockIdx.y*128; n0 = blockIdx.x*128;
        Ah = g_hnTh + ((size_t)b*N_ + m0)*C_;  Al = g_hnTl + ((size_t)b*N_ + m0)*C_;
        Bh = g_w4h + (size_t)which*C_*C_ + (size_t)n0*C_;
        Bl = g_w4l + (size_t)which*C_*C_ + (size_t)n0*C_;
    } else {
        m0 = blockIdx.x*128; n0 = blockIdx.y*128;
        Ah = g_w4h + 2*(size_t)C_*C_ + (size_t)m0*C_;
        Al = g_w4l + 2*(size_t)C_*C_ + (size_t)m0*C_;
        Bh = g_hnTh + ((size_t)b*N_ + n0)*C_;  Bl = g_hnTl + ((size_t)b*N_ + n0)*C_;
    }

    float acc[2][8][4];
    #pragma unroll
    for (int mf=0;mf<2;mf++)
        #pragma unroll
        for (int nf=0;nf<8;nf++)
            #pragma unroll
            for (int r=0;r<4;r++) acc[mf][nf][r] = 0.f;

    mma_core<128,1>(Ah, Al, Bh, Bl, C_, C_, sb, acc);

    const int tid = threadIdx.x, lane = tid & 31, wid = tid >> 5;
    const int wm = (wid & 3) * 32, wn = (wid >> 2) * 64;
    const int gid = lane >> 2, tig = lane & 3;
    const float* bias = (which==0)?bq:(which==1)?bk:bv;
    #pragma unroll
    for (int mf=0;mf<2;mf++)
        #pragma unroll
        for (int nf=0;nf<8;nf++)
            #pragma unroll
            for (int h=0;h<2;h++){
                int m = m0 + wm + mf*16 + gid + h*8;
                int n = n0 + wn + nf*8 + tig*2;
                float v0 = acc[mf][nf][h*2], v1 = acc[mf][nf][h*2+1];
                uint32_t hi, lo;
                size_t off;
                if (which < 2){
                    v0 += bias[n]; v1 += bias[n+1];
                    off = ((size_t)b*N_ + m)*C_ + n;
                    hsplit2(v0, v1, hi, lo);
                    if (which == 0){ *(uint32_t*)&g_qT[off] = hi; }   // q: single fp16
                    else           { *(uint32_t*)&g_kTh[off] = hi; *(uint32_t*)&g_kTl[off] = lo; }
                } else {
                    float bm = bias[m]; v0 += bm; v1 += bm;
                    off = (size_t)b*CN + (size_t)m*N_ + n;
                    hsplit2(v0, v1, hi, lo);
                    *(uint32_t*)&g_vh[off] = hi; *(uint32_t*)&g_vl[off] = lo;
                }
            }
}

// ---------------- scores: e = exp(q.k^T / 16) -> eh/el (i,m) + partial sums ----------------
// 2-term fp16 (q single x k hi/lo); BN=128 -> 48KB/stage -> 2 CTAs/SM.
// grid: x = m-tile (32), y = i-tile (32), z = b; 256 threads
__global__ void __launch_bounds__(256,2) scores_mma()
{
    extern __shared__ char smem[];
    uint32_t sb = smem_u32(smem);
    const int tid = threadIdx.x;
    const int b  = blockIdx.z;
    const int m0 = blockIdx.x*128;
    const int i0 = blockIdx.y*128;

    float acc[2][8][4];
    #pragma unroll
    for (int mf=0;mf<2;mf++)
        #pragma unroll
        for (int nf=0;nf<8;nf++)
            #pragma unroll
            for (int r=0;r<4;r++) acc[mf][nf][r] = 0.f;

    const hf* Ah = g_qT + ((size_t)b*N_ + i0)*C_;
    mma_core<128,0>(Ah, Ah,
                    g_kTh + ((size_t)b*N_ + m0)*C_, g_kTl + ((size_t)b*N_ + m0)*C_,
                    C_, C_, sb, acc);

    // exp into smT[i_local 128][m_local 128] (pitch 129)
    float* smT = (float*)smem;
    const int lane = tid & 31, wid = tid >> 5;
    const int wm = (wid & 3) * 32, wn = (wid >> 2) * 64;
    const int gid = lane >> 2, tig = lane & 3;
    #pragma unroll
    for (int mf=0;mf<2;mf++)
        #pragma unroll
        for (int nf=0;nf<8;nf++)
            #pragma unroll
            for (int h=0;h<2;h++){
                int il = wm + mf*16 + gid + h*8;
                int ml = wn + nf*8 + tig*2;
                smT[il*129 + ml]     = __expf(acc[mf][nf][h*2]   * 0.0625f);
                smT[il*129 + ml + 1] = __expf(acc[mf][nf][h*2+1] * 0.0625f);
            }
    __syncthreads();

    // e fp16 hi/lo in (i, m), coalesced: 128 rows x 2 halves of 64
    {
        int il = tid >> 1, half = tid & 1;
        const float* row = smT + il*129 + half*64;
        size_t go = ((size_t)b*N_ + i0 + il)*N_ + m0 + half*64;
        #pragma unroll
        for (int cb=0; cb<64; cb+=8){
            uint32_t hb[4], lb[4];
            #pragma unroll
            for (int q=0;q<4;q++)
                hsplit2(row[cb+q*2], row[cb+q*2+1], hb[q], lb[q]);
            *(uint4*)&g_eh[go + cb] = *(uint4*)hb;
            *(uint4*)&g_el[go + cb] = *(uint4*)lb;
        }
    }

    // deterministic partial row sums over this 128-wide m-tile
    if (tid < 128){
        float s = 0.f;
        #pragma unroll 8
        for (int m=0;m<128;m++) s += smT[tid*129 + m];
        g_partial[((size_t)b*N_ + i0 + tid)*32 + blockIdx.x] = s;
    }
}

// ---------------- reduce partials -> reciprocal row sums ----------------
__global__ void rowsum_inv(){
    int idx = blockIdx.x*256 + threadIdx.x;
    float s = 0.f;
    #pragma unroll
    for (int t=0;t<32;t++) s += g_partial[(size_t)idx*32 + t];
    g_rinv[idx] = 1.0f/s;
}

// ---------------- w_out[b][m][i] = (eh+el)[b][i][m] * rinv[b][i]  (tiled transpose) ----------------
__global__ void __launch_bounds__(256) norm_t(float* __restrict__ w_out){
    __shared__ float t[64][65];
    const int b = blockIdx.z, m0 = blockIdx.x*64, i0 = blockIdx.y*64;
    const int tid = threadIdx.x;
    const hf* eh = g_eh + ((size_t)b*N_ + i0)*N_ + m0;
    const hf* el = g_el + ((size_t)b*N_ + i0)*N_ + m0;
    const int r = tid >> 2, cc = tid & 3;
    const float rv = g_rinv[(size_t)b*N_ + i0 + r];
    #pragma unroll
    for (int it=0; it<2; it++){
        int c8 = cc + it*4;
        uint4 hv4 = *(const uint4*)(eh + (size_t)r*N_ + c8*8);
        uint4 lv4 = *(const uint4*)(el + (size_t)r*N_ + c8*8);
        const hf* hp = (const hf*)&hv4;
        const hf* lp = (const hf*)&lv4;
        #pragma unroll
        for (int j=0;j<8;j++)
            t[r][c8*8+j] = (__half2float(hp[j]) + __half2float(lp[j])) * rv;
    }
    __syncthreads();
    const int mr = tid >> 2, ic = tid & 3;
    float* wrow = w_out + (size_t)b*N_*N_ + (size_t)(m0+mr)*N_ + i0;
    #pragma unroll
    for (int it=0; it<4; it++){
        int i4 = ic + it*4;
        float4 o;
        o.x = t[i4*4+0][mr]; o.y = t[i4*4+1][mr];
        o.z = t[i4*4+2][mr]; o.w = t[i4*4+3][mr];
        *(float4*)(wrow + i4*4) = o;
    }
}

// ---------------- PV: hvT[i][c] = (sum_m v[c][m] e[i][m]) * rinv[i], fp16 hi/lo ----------------
// full 3-term; 128(c) x 64(i) tiles -> 48KB/stage -> 2 CTAs/SM; grid (64, 2, 2)
__global__ void __launch_bounds__(256,2) pv_mma()
{
    extern __shared__ char smem[];
    uint32_t sb = smem_u32(smem);
    const int tid = threadIdx.x;
    const int b  = blockIdx.z;
    const int c0 = blockIdx.y*128;
    const int i0 = blockIdx.x*64;

    float acc[2][4][4];
    #pragma unroll
    for (int mf=0;mf<2;mf++)
        #pragma unroll
        for (int nf=0;nf<4;nf++)
            #pragma unroll
            for (int r=0;r<4;r++) acc[mf][nf][r] = 0.f;

    mma_core<64,1>(g_vh + (size_t)b*CN + (size_t)c0*N_, g_vl + (size_t)b*CN + (size_t)c0*N_,
                   g_eh + ((size_t)b*N_ + i0)*N_,       g_el + ((size_t)b*N_ + i0)*N_,
                   N_, N_, sb, acc);

    // stage (i, c) f32 with rinv applied, then write hvT (i, c) hi/lo coalesced
    float* smT = (float*)smem;                 // [i_local 64][pitch 129]
    const float* rinv = g_rinv + (size_t)b*N_ + i0;
    const int lane = tid & 31, wid = tid >> 5;
    const int wm = (wid & 3) * 32, wn = (wid >> 2) * 32;
    const int gid = lane >> 2, tig = lane & 3;
    #pragma unroll
    for (int mf=0;mf<2;mf++)
        #pragma unroll
        for (int nf=0;nf<4;nf++)
            #pragma unroll
            for (int h=0;h<2;h++){
                int c = wm + mf*16 + gid + h*8;
                int n = wn + nf*8 + tig*2;
                smT[n*129 + c]     = acc[mf][nf][h*2]   * rinv[n];
                smT[(n+1)*129 + c] = acc[mf][nf][h*2+1] * rinv[n+1];
            }
    __syncthreads();
    {
        int il = tid >> 2, qq = tid & 3;       // 64 rows x 4 quarters of 32 c
        const float* row = smT + il*129 + qq*32;
        size_t go = ((size_t)b*N_ + i0 + il)*C_ + c0 + qq*32;
        #pragma unroll
        for (int cb=0; cb<32; cb+=8){
            uint32_t hb[4], lb[4];
            #pragma unroll
            for (int q=0;q<4;q++)
                hsplit2(row[cb+q*2], row[cb+q*2+1], hb[q], lb[q]);
            *(uint4*)&g_hvTh[go + cb] = *(uint4*)hb;
            *(uint4*)&g_hvTl[go + cb] = *(uint4*)lb;
        }
    }
}

// ---------------- proj: out[b][o][n] = x + sum_c wp[o][c] hvT[n][c] + bp[o] ----------------
// grid: x = n-tile (32), y = o-tile (2), z = b; 256 threads
__global__ void __launch_bounds__(256) proj_mma(
    float* __restrict__ out, const float* __restrict__ x, const float* __restrict__ bp)
{
    extern __shared__ char smem[];
    uint32_t sb = smem_u32(smem);
    const int b  = blockIdx.z;
    const int m0 = blockIdx.y*128;     // o
    const int n0 = blockIdx.x*128;     // n

    float acc[2][8][4];
    #pragma unroll
    for (int mf=0;mf<2;mf++)
        #pragma unroll
        for (int nf=0;nf<8;nf++)
            #pragma unroll
            for (int r=0;r<4;r++) acc[mf][nf][r] = 0.f;

    mma_core<128,1>(g_w4h + 3*(size_t)C_*C_ + (size_t)m0*C_, g_w4l + 3*(size_t)C_*C_ + (size_t)m0*C_,
                    g_hvTh + ((size_t)b*N_ + n0)*C_,         g_hvTl + ((size_t)b*N_ + n0)*C_,
                    C_, C_, sb, acc);

    const int tid = threadIdx.x, lane = tid & 31, wid = tid >> 5;
    const int wm = (wid & 3) * 32, wn = (wid >> 2) * 64;
    const int gid = lane >> 2, tig = lane & 3;
    #pragma unroll
    for (int mf=0;mf<2;mf++)
        #pragma unroll
        for (int nf=0;nf<8;nf++)
            #pragma unroll
            for (int h=0;h<2;h++){
                int m = m0 + wm + mf*16 + gid + h*8;
                int n = n0 + wn + nf*8 + tig*2;
                size_t off = (size_t)b*CN + (size_t)m*N_ + n;
                float bm = bp[m];
                float2 st;
                st.x = acc[mf][nf][h*2]   + bm + x[off];
                st.y = acc[mf][nf][h*2+1] + bm + x[off+1];
                *(float2*)&out[off] = st;
            }
}

// ---------------- host launch ----------------
extern "C" void kernel_launch(void* const* d_in, const int* in_sizes, int n_in,
                              void* d_out, int out_size){
    const float* x    = (const float*)d_in[0];
    const float* gma  = (const float*)d_in[1];
    const float* bta  = (const float*)d_in[2];
    const float* wq   = (const float*)d_in[3];
    const float* bq   = (const float*)d_in[4];
    const float* wk   = (const float*)d_in[5];
    const float* bk   = (const float*)d_in[6];
    const float* wv   = (const float*)d_in[7];
    const float* bv   = (const float*)d_in[8];
    const float* wp   = (const float*)d_in[9];
    const float* bp   = (const float*)d_in[10];
    float* out   = (float*)d_out;
    float* w_out = out + (size_t)B_*CN;

    cudaFuncSetAttribute(qkv_mma,    cudaFuncAttributeMaxDynamicSharedMemorySize, SMEM_FULL);
    cudaFuncSetAttribute(scores_mma, cudaFuncAttributeMaxDynamicSharedMemorySize, SMEM_SC);
    cudaFuncSetAttribute(pv_mma,     cudaFuncAttributeMaxDynamicSharedMemorySize, SMEM_SC);
    cudaFuncSetAttribute(proj_mma,   cudaFuncAttributeMaxDynamicSharedMemorySize, SMEM_FULL);

    conv_w4<<<512, 256>>>(wq, wk, wv, wp);
    gn_kernel<<<64, 256>>>(x, gma, bta);

    // q, k, v in one launch (384 CTAs)
    qkv_mma<<<dim3(2,32,6), 256, SMEM_FULL>>>(bq, bk, bv);

    // e = exp(qk/16) -> fp16 hi/lo (i,m) + deterministic partials (2-term fp16)
    scores_mma<<<dim3(32,32,2), 256, SMEM_SC>>>();
    rowsum_inv<<<32, 256>>>();

    // w_out[b][m][i] = (eh+el)*rinv (transposing normalize)
    norm_t<<<dim3(64,64,2), 256>>>(w_out);

    // hvT (b, n, c) fp16 hi/lo (full 3-term)
    pv_mma<<<dim3(64,2,2), 256, SMEM_SC>>>();

    // out = x + wp*hv + bp
    proj_mma<<<dim3(32,2,2), 256, SMEM_FULL>>>(out, x, bp);
}

// round 16
// speedup vs baseline: 1.4475x; 1.4475x over previous
#include <cuda_runtime.h>
#include <cuda_bf16.h>
#include <cstdint>
#include <cstddef>

#define B_ 2
#define C_ 256
#define N_ 4096
#define CN (C_*N_)

// ---------------- scratch (static __device__, no allocation) ----------------
__device__ float g_partial[B_*N_*64];  // per (b,i,mtile64) partial exp-sums
__device__ float g_rinv[B_*N_];        // 1/rowsum

// bf16 hi/lo split operands
__device__ __nv_bfloat16 g_hnTh[B_*N_*C_], g_hnTl[B_*N_*C_]; // hn^T (b, n, c)
__device__ __nv_bfloat16 g_w4h[4*C_*C_],   g_w4l[4*C_*C_];   // wq, wk, wv, wp (o, c)
__device__ __nv_bfloat16 g_qTh[B_*N_*C_],  g_qTl[B_*N_*C_];  // qT (b, n, c)
__device__ __nv_bfloat16 g_kTh[B_*N_*C_],  g_kTl[B_*N_*C_];  // kT (b, n, c)
__device__ __nv_bfloat16 g_vh [B_*CN],     g_vl [B_*CN];     // v  (b, c, n)
__device__ __nv_bfloat16 g_hvTh[B_*N_*C_], g_hvTl[B_*N_*C_]; // hv^T (b, n, c)
__device__ __nv_bfloat16 g_eh [(size_t)B_*N_*N_];            // e (b, i, m) hi
__device__ __nv_bfloat16 g_el [(size_t)B_*N_*N_];            // e (b, i, m) lo

// ---------------- helpers ----------------
__device__ __forceinline__ uint32_t smem_u32(const void* p){
    uint32_t a;
    asm("{ .reg .u64 t; cvta.to.shared.u64 t, %1; cvt.u32.u64 %0, t; }" : "=r"(a) : "l"(p));
    return a;
}
__device__ __forceinline__ uint32_t sw128(uint32_t o){ return o ^ ((o >> 3) & 0x70); }

__device__ __forceinline__ void ldsm4(uint32_t r[4], uint32_t addr){
    asm volatile("ldmatrix.sync.aligned.m8n8.x4.shared.b16 {%0,%1,%2,%3}, [%4];"
        : "=r"(r[0]), "=r"(r[1]), "=r"(r[2]), "=r"(r[3]) : "r"(addr));
}
__device__ __forceinline__ void mma16816(float d[4], const uint32_t a[4], uint32_t b0, uint32_t b1){
    asm volatile("mma.sync.aligned.m16n8k16.row.col.f32.bf16.bf16.f32 "
        "{%0,%1,%2,%3}, {%4,%5,%6,%7}, {%8,%9}, {%0,%1,%2,%3};"
        : "+f"(d[0]), "+f"(d[1]), "+f"(d[2]), "+f"(d[3])
        : "r"(a[0]), "r"(a[1]), "r"(a[2]), "r"(a[3]), "r"(b0), "r"(b1));
}
__device__ __forceinline__ void cpa16(uint32_t dst, const void* src){
    asm volatile("cp.async.cg.shared.global [%0], [%1], 16;"
        :: "r"(dst), "l"(__cvta_generic_to_global(src)) : "memory");
}
#define CP_COMMIT() asm volatile("cp.async.commit_group;" ::: "memory")
#define CP_WAIT1()  asm volatile("cp.async.wait_group 1;" ::: "memory")
#define CP_WAIT0()  asm volatile("cp.async.wait_group 0;" ::: "memory")

__device__ __forceinline__ void bfsplit2(float v0, float v1, uint32_t& hi, uint32_t& lo){
    __nv_bfloat16 h0 = __float2bfloat16(v0);
    __nv_bfloat16 h1 = __float2bfloat16(v1);
    __nv_bfloat16 l0 = __float2bfloat16(v0 - __bfloat162float(h0));
    __nv_bfloat16 l1 = __float2bfloat16(v1 - __bfloat162float(h1));
    hi = (uint32_t)__bfloat16_as_ushort(h0) | ((uint32_t)__bfloat16_as_ushort(h1) << 16);
    lo = (uint32_t)__bfloat16_as_ushort(l0) | ((uint32_t)__bfloat16_as_ushort(l1) << 16);
}

// ---------------- templated 2-stage 128xBN mma core (full 3-term bf16 hi/lo) ----------------
// A: 128 rows k-major (hi+lo); B: BN rows k-major (hi+lo).
// Terms per k16: ah*bh + ah*bl + al*bh. Stage: AH@0, AL@16K, BH@32K, BL@32K+BN*128.
template<int BN>
__device__ __forceinline__ void mc_load(
    const __nv_bfloat16* __restrict__ Ah, const __nv_bfloat16* __restrict__ Al,
    const __nv_bfloat16* __restrict__ Bh, const __nv_bfloat16* __restrict__ Bl,
    int stride, int kk, uint32_t sbuf)
{
    constexpr int BH_OFF = 32768;
    constexpr int BL_OFF = BH_OFF + BN*128;
    const int tid = threadIdx.x;
    #pragma unroll
    for (int t = 0; t < 4; t++){
        int idx = tid + t*256;
        int r = idx >> 3, c16 = idx & 7;
        uint32_t so = sw128((uint32_t)(r*128 + c16*16));
        size_t go = (size_t)r*stride + kk + c16*8;
        cpa16(sbuf + so, Ah + go);
        cpa16(sbuf + 16384 + so, Al + go);
    }
    #pragma unroll
    for (int t = 0; t < BN/32; t++){
        int idx = tid + t*256;
        int r = idx >> 3, c16 = idx & 7;
        uint32_t so = sw128((uint32_t)(r*128 + c16*16));
        size_t go = (size_t)r*stride + kk + c16*8;
        cpa16(sbuf + BH_OFF + so, Bh + go);
        cpa16(sbuf + BL_OFF + so, Bl + go);
    }
}

template<int BN>
__device__ __forceinline__ void mc_compute(uint32_t sbuf, float acc[2][BN/16][4])
{
    constexpr int BH_OFF = 32768;
    constexpr int BL_OFF = BH_OFF + BN*128;
    const int tid  = threadIdx.x;
    const int lane = tid & 31, wid = tid >> 5;
    const int wm = (wid & 3) * 32, wn = (wid >> 2) * (BN/2);
    const int lrow = ((lane >> 3) & 1) * 8 + (lane & 7);
    const int lk   = (lane >> 4) * 8;
    #pragma unroll
    for (int k16 = 0; k16 < 4; k16++){
        uint32_t ah[2][4], al[2][4];
        #pragma unroll
        for (int mf = 0; mf < 2; mf++){
            uint32_t off = sw128((uint32_t)((wm + mf*16 + lrow)*128 + (k16*16 + lk)*2));
            ldsm4(ah[mf], sbuf + off);
            ldsm4(al[mf], sbuf + 16384 + off);
        }
        #pragma unroll
        for (int nf2 = 0; nf2 < BN/32; nf2++){
            uint32_t boff = sw128((uint32_t)((wn + nf2*16 + lrow)*128 + (k16*16 + lk)*2));
            uint32_t bh[4], bl[4];
            ldsm4(bh, sbuf + BH_OFF + boff);
            ldsm4(bl, sbuf + BL_OFF + boff);
            #pragma unroll
            for (int mf = 0; mf < 2; mf++){
                #pragma unroll
                for (int w = 0; w < 2; w++){
                    int nf = nf2*2 + w;
                    mma16816(acc[mf][nf], ah[mf], bh[w], bh[w+2]);
                    mma16816(acc[mf][nf], ah[mf], bl[w], bl[w+2]);
                    mma16816(acc[mf][nf], al[mf], bh[w], bh[w+2]);
                }
            }
        }
    }
}

template<int BN>
__device__ __forceinline__ void mma_core(
    const __nv_bfloat16* __restrict__ Ah, const __nv_bfloat16* __restrict__ Al,
    const __nv_bfloat16* __restrict__ Bh, const __nv_bfloat16* __restrict__ Bl,
    int stride, int K, uint32_t sb, float acc[2][BN/16][4])
{
    constexpr int STAGE = 32768 + BN*256;
    const int nch = K >> 6;
    mc_load<BN>(Ah, Al, Bh, Bl, stride, 0, sb);
    CP_COMMIT();
    for (int c = 0; c < nch; c++){
        if (c + 1 < nch){
            mc_load<BN>(Ah, Al, Bh, Bl, stride, (c+1)*64, sb + ((c+1)&1)*STAGE);
            CP_COMMIT();
            CP_WAIT1();
        } else {
            CP_WAIT0();
        }
        __syncthreads();
        mc_compute<BN>(sb + (c&1)*STAGE, acc);
        __syncthreads();
    }
}

#define SMEM_SC (2*49152)      // BN=64: 48KB/stage -> 96KB/CTA -> 2 CTAs/SM

// ---------------- wq/wk/wv/wp -> bf16 hi/lo (layout unchanged: (o, c) k-major) ----------------
__global__ void conv_w4(const float* __restrict__ wq, const float* __restrict__ wk,
                        const float* __restrict__ wv, const float* __restrict__ wp){
    int idx = blockIdx.x*256 + threadIdx.x;       // 0 .. 4*32768-1 (pairs)
    int which = idx >> 15;
    int pair  = idx & 32767;
    const float* src = (which==0)?wq:(which==1)?wk:(which==2)?wv:wp;
    float v0 = src[pair*2], v1 = src[pair*2+1];
    uint32_t hi, lo;
    bfsplit2(v0, v1, hi, lo);
    *(uint32_t*)&g_w4h[(size_t)which*C_*C_ + pair*2] = hi;
    *(uint32_t*)&g_w4l[(size_t)which*C_*C_ + pair*2] = lo;
}

// ---------------- GroupNorm -> hn^T (b, n, c) bf16 hi/lo ----------------
__global__ void gn_kernel(const float* __restrict__ x, const float* __restrict__ gma,
                          const float* __restrict__ bta){
    const int bg = blockIdx.x;                 // 64 = b*32 + grp
    const int b = bg >> 5, grp = bg & 31;
    const size_t base = (size_t)b*CN + (size_t)grp*8*N_;
    const float* xp = x + base;
    const int tid = threadIdx.x;
    float s = 0.f, sq = 0.f;
    for (int i = tid; i < 8*N_; i += 256){ float v = xp[i]; s += v; sq += v*v; }
    __shared__ float ss[256], sk[256];
    ss[tid]=s; sk[tid]=sq; __syncthreads();
    for (int o=128;o>0;o>>=1){
        if (tid < o){ ss[tid]+=ss[tid+o]; sk[tid]+=sk[tid+o]; }
        __syncthreads();
    }
    const float inv = 1.0f/(8.0f*N_);
    float mu = ss[0]*inv;
    float var = sk[0]*inv - mu*mu;
    float rs = rsqrtf(var + 1e-6f);
    float gm[8], bt[8];
    #pragma unroll
    for (int ch=0; ch<8; ch++){ gm[ch] = gma[grp*8+ch]*rs; bt[ch] = bta[grp*8+ch]; }
    for (int n = tid; n < N_; n += 256){
        uint32_t hi[4], lo[4];
        #pragma unroll
        for (int p=0; p<4; p++){
            float v0 = (xp[(size_t)(p*2  )*N_ + n] - mu)*gm[p*2]   + bt[p*2];
            float v1 = (xp[(size_t)(p*2+1)*N_ + n] - mu)*gm[p*2+1] + bt[p*2+1];
            bfsplit2(v0, v1, hi[p], lo[p]);
        }
        size_t off = ((size_t)b*N_ + n)*C_ + grp*8;
        *(uint4*)&g_hnTh[off] = *(uint4*)hi;
        *(uint4*)&g_hnTl[off] = *(uint4*)lo;
    }
}

// ---------------- q/k: qT[n][o] = sum_c hnT[n][c] w[o][c] + b[o] ----------------
// BN=64, 2 CTAs/SM; grid: x = o-tile (4), y = n-tile (32), z = which*2 + b (4)
__global__ void __launch_bounds__(256,2) qk_mma(
    const float* __restrict__ bq, const float* __restrict__ bk)
{
    extern __shared__ char smem[];
    uint32_t sb = smem_u32(smem);
    const int z = blockIdx.z;
    const int which = z >> 1, b = z & 1;
    const int m0 = blockIdx.y*128;     // n rows
    const int n0 = blockIdx.x*64;      // o cols

    float acc[2][4][4];
    #pragma unroll
    for (int mf=0;mf<2;mf++)
        #pragma unroll
        for (int nf=0;nf<4;nf++)
            #pragma unroll
            for (int r=0;r<4;r++) acc[mf][nf][r] = 0.f;

    mma_core<64>(g_hnTh + ((size_t)b*N_ + m0)*C_, g_hnTl + ((size_t)b*N_ + m0)*C_,
                 g_w4h + (size_t)which*C_*C_ + (size_t)n0*C_,
                 g_w4l + (size_t)which*C_*C_ + (size_t)n0*C_,
                 C_, C_, sb, acc);

    const int tid = threadIdx.x, lane = tid & 31, wid = tid >> 5;
    const int wm = (wid & 3) * 32, wn = (wid >> 2) * 32;
    const int gid = lane >> 2, tig = lane & 3;
    const float* bias = which ? bk : bq;
    #pragma unroll
    for (int mf=0;mf<2;mf++)
        #pragma unroll
        for (int nf=0;nf<4;nf++)
            #pragma unroll
            for (int h=0;h<2;h++){
                int m = m0 + wm + mf*16 + gid + h*8;
                int n = n0 + wn + nf*8 + tig*2;
                float v0 = acc[mf][nf][h*2]   + bias[n];
                float v1 = acc[mf][nf][h*2+1] + bias[n+1];
                uint32_t hi, lo;
                bfsplit2(v0, v1, hi, lo);
                size_t off = ((size_t)b*N_ + m)*C_ + n;
                if (which == 0){ *(uint32_t*)&g_qTh[off] = hi; *(uint32_t*)&g_qTl[off] = lo; }
                else           { *(uint32_t*)&g_kTh[off] = hi; *(uint32_t*)&g_kTl[off] = lo; }
            }
}

// ---------------- v: v[o][n] = sum_c wv[o][c] hnT[n][c] + b[o] ----------------
// BN=64, 2 CTAs/SM; grid: x = n-tile (64), y = o-tile (2), z = b
__global__ void __launch_bounds__(256,2) v_mma(const float* __restrict__ bv)
{
    extern __shared__ char smem[];
    uint32_t sb = smem_u32(smem);
    const int b  = blockIdx.z;
    const int m0 = blockIdx.y*128;     // o rows
    const int n0 = blockIdx.x*64;      // n cols

    float acc[2][4][4];
    #pragma unroll
    for (int mf=0;mf<2;mf++)
        #pragma unroll
        for (int nf=0;nf<4;nf++)
            #pragma unroll
            for (int r=0;r<4;r++) acc[mf][nf][r] = 0.f;

    mma_core<64>(g_w4h + 2*(size_t)C_*C_ + (size_t)m0*C_,
                 g_w4l + 2*(size_t)C_*C_ + (size_t)m0*C_,
                 g_hnTh + ((size_t)b*N_ + n0)*C_, g_hnTl + ((size_t)b*N_ + n0)*C_,
                 C_, C_, sb, acc);

    const int tid = threadIdx.x, lane = tid & 31, wid = tid >> 5;
    const int wm = (wid & 3) * 32, wn = (wid >> 2) * 32;
    const int gid = lane >> 2, tig = lane & 3;
    #pragma unroll
    for (int mf=0;mf<2;mf++)
        #pragma unroll
        for (int nf=0;nf<4;nf++)
            #pragma unroll
            for (int h=0;h<2;h++){
                int m = m0 + wm + mf*16 + gid + h*8;
                int n = n0 + wn + nf*8 + tig*2;
                float bm = bv[m];
                float v0 = acc[mf][nf][h*2]   + bm;
                float v1 = acc[mf][nf][h*2+1] + bm;
                uint32_t hi, lo;
                bfsplit2(v0, v1, hi, lo);
                size_t off = (size_t)b*CN + (size_t)m*N_ + n;
                *(uint32_t*)&g_vh[off] = hi; *(uint32_t*)&g_vl[off] = lo;
            }
}

// ---------------- scores: e = exp(q.k^T / 16) -> eh/el (i,m) + partial sums ----------------
// FULL 3-term; 128(i) x 64(m) tiles -> 2 CTAs/SM.
// grid: x = m-tile (64), y = i-tile (32), z = b; 256 threads
__global__ void __launch_bounds__(256,2) scores_mma()
{
    extern __shared__ char smem[];
    uint32_t sb = smem_u32(smem);
    const int tid = threadIdx.x;
    const int b  = blockIdx.z;
    const int m0 = blockIdx.x*64;
    const int i0 = blockIdx.y*128;

    float acc[2][4][4];
    #pragma unroll
    for (int mf=0;mf<2;mf++)
        #pragma unroll
        for (int nf=0;nf<4;nf++)
            #pragma unroll
            for (int r=0;r<4;r++) acc[mf][nf][r] = 0.f;

    mma_core<64>(g_qTh + ((size_t)b*N_ + i0)*C_, g_qTl + ((size_t)b*N_ + i0)*C_,
                 g_kTh + ((size_t)b*N_ + m0)*C_, g_kTl + ((size_t)b*N_ + m0)*C_,
                 C_, C_, sb, acc);

    // exp into smT[i_local 128][m_local 64] (pitch 65)
    float* smT = (float*)smem;
    const int lane = tid & 31, wid = tid >> 5;
    const int wm = (wid & 3) * 32, wn = (wid >> 2) * 32;
    const int gid = lane >> 2, tig = lane & 3;
    #pragma unroll
    for (int mf=0;mf<2;mf++)
        #pragma unroll
        for (int nf=0;nf<4;nf++)
            #pragma unroll
            for (int h=0;h<2;h++){
                int il = wm + mf*16 + gid + h*8;
                int ml = wn + nf*8 + tig*2;
                smT[il*65 + ml]     = __expf(acc[mf][nf][h*2]   * 0.0625f);
                smT[il*65 + ml + 1] = __expf(acc[mf][nf][h*2+1] * 0.0625f);
            }
    __syncthreads();

    // e bf16 hi/lo in (i, m), coalesced: 128 rows x 2 halves of 32
    {
        int il = tid >> 1, half = tid & 1;
        const float* row = smT + il*65 + half*32;
        size_t go = ((size_t)b*N_ + i0 + il)*N_ + m0 + half*32;
        #pragma unroll
        for (int cb=0; cb<32; cb+=8){
            uint32_t hb[4], lb[4];
            #pragma unroll
            for (int q=0;q<4;q++)
                bfsplit2(row[cb+q*2], row[cb+q*2+1], hb[q], lb[q]);
            *(uint4*)&g_eh[go + cb] = *(uint4*)hb;
            *(uint4*)&g_el[go + cb] = *(uint4*)lb;
        }
    }

    // deterministic partial row sums over this 64-wide m-tile
    if (tid < 128){
        float s = 0.f;
        #pragma unroll 8
        for (int m=0;m<64;m++) s += smT[tid*65 + m];
        g_partial[((size_t)b*N_ + i0 + tid)*64 + blockIdx.x] = s;
    }
}

// ---------------- reduce partials -> reciprocal row sums ----------------
__global__ void rowsum_inv(){
    int idx = blockIdx.x*256 + threadIdx.x;
    float s = 0.f;
    #pragma unroll
    for (int t=0;t<64;t++) s += g_partial[(size_t)idx*64 + t];
    g_rinv[idx] = 1.0f/s;
}

// ---------------- w_out[b][m][i] = (eh+el)[b][i][m] * rinv[b][i]  (tiled transpose) ----------------
__global__ void __launch_bounds__(256) norm_t(float* __restrict__ w_out){
    __shared__ float t[64][65];
    const int b = blockIdx.z, m0 = blockIdx.x*64, i0 = blockIdx.y*64;
    const int tid = threadIdx.x;
    const __nv_bfloat16* eh = g_eh + ((size_t)b*N_ + i0)*N_ + m0;
    const __nv_bfloat16* el = g_el + ((size_t)b*N_ + i0)*N_ + m0;
    const int r = tid >> 2, cc = tid & 3;
    const float rv = g_rinv[(size_t)b*N_ + i0 + r];
    #pragma unroll
    for (int it=0; it<2; it++){
        int c8 = cc + it*4;
        uint4 hv4 = *(const uint4*)(eh + (size_t)r*N_ + c8*8);
        uint4 lv4 = *(const uint4*)(el + (size_t)r*N_ + c8*8);
        const __nv_bfloat16* hp = (const __nv_bfloat16*)&hv4;
        const __nv_bfloat16* lp = (const __nv_bfloat16*)&lv4;
        #pragma unroll
        for (int j=0;j<8;j++)
            t[r][c8*8+j] = (__bfloat162float(hp[j]) + __bfloat162float(lp[j])) * rv;
    }
    __syncthreads();
    const int mr = tid >> 2, ic = tid & 3;
    float* wrow = w_out + (size_t)b*N_*N_ + (size_t)(m0+mr)*N_ + i0;
    #pragma unroll
    for (int it=0; it<4; it++){
        int i4 = ic + it*4;
        float4 o;
        o.x = t[i4*4+0][mr]; o.y = t[i4*4+1][mr];
        o.z = t[i4*4+2][mr]; o.w = t[i4*4+3][mr];
        *(float4*)(wrow + i4*4) = o;
    }
}

// ---------------- PV: hvT[i][c] = (sum_m v[c][m] e[i][m]) * rinv[i], bf16 hi/lo ----------------
// 128(c) x 64(i) tiles -> 2 CTAs/SM; grid (64, 2, 2); 256 threads
__global__ void __launch_bounds__(256,2) pv_mma()
{
    extern __shared__ char smem[];
    uint32_t sb = smem_u32(smem);
    const int tid = threadIdx.x;
    const int b  = blockIdx.z;
    const int c0 = blockIdx.y*128;
    const int i0 = blockIdx.x*64;

    float acc[2][4][4];
    #pragma unroll
    for (int mf=0;mf<2;mf++)
        #pragma unroll
        for (int nf=0;nf<4;nf++)
            #pragma unroll
            for (int r=0;r<4;r++) acc[mf][nf][r] = 0.f;

    mma_core<64>(g_vh + (size_t)b*CN + (size_t)c0*N_, g_vl + (size_t)b*CN + (size_t)c0*N_,
                 g_eh + ((size_t)b*N_ + i0)*N_,       g_el + ((size_t)b*N_ + i0)*N_,
                 N_, N_, sb, acc);

    // stage (i, c) f32 with rinv applied, then write hvT (i, c) hi/lo coalesced
    float* smT = (float*)smem;                 // [i_local 64][pitch 129]
    const float* rinv = g_rinv + (size_t)b*N_ + i0;
    const int lane = tid & 31, wid = tid >> 5;
    const int wm = (wid & 3) * 32, wn = (wid >> 2) * 32;
    const int gid = lane >> 2, tig = lane & 3;
    #pragma unroll
    for (int mf=0;mf<2;mf++)
        #pragma unroll
        for (int nf=0;nf<4;nf++)
            #pragma unroll
            for (int h=0;h<2;h++){
                int c = wm + mf*16 + gid + h*8;
                int n = wn + nf*8 + tig*2;
                smT[n*129 + c]     = acc[mf][nf][h*2]   * rinv[n];
                smT[(n+1)*129 + c] = acc[mf][nf][h*2+1] * rinv[n+1];
            }
    __syncthreads();
    {
        int il = tid >> 2, qq = tid & 3;       // 64 rows x 4 quarters of 32 c
        const float* row = smT + il*129 + qq*32;
        size_t go = ((size_t)b*N_ + i0 + il)*C_ + c0 + qq*32;
        #pragma unroll
        for (int cb=0; cb<32; cb+=8){
            uint32_t hb[4], lb[4];
            #pragma unroll
            for (int q=0;q<4;q++)
                bfsplit2(row[cb+q*2], row[cb+q*2+1], hb[q], lb[q]);
            *(uint4*)&g_hvTh[go + cb] = *(uint4*)hb;
            *(uint4*)&g_hvTl[go + cb] = *(uint4*)lb;
        }
    }
}

// ---------------- proj: out[b][o][n] = x + sum_c wp[o][c] hvT[n][c] + bp[o] ----------------
// BN=64, 2 CTAs/SM; grid: x = n-tile (64), y = o-tile (2), z = b
__global__ void __launch_bounds__(256,2) proj_mma(
    float* __restrict__ out, const float* __restrict__ x, const float* __restrict__ bp)
{
    extern __shared__ char smem[];
    uint32_t sb = smem_u32(smem);
    const int b  = blockIdx.z;
    const int m0 = blockIdx.y*128;     // o
    const int n0 = blockIdx.x*64;      // n

    float acc[2][4][4];
    #pragma unroll
    for (int mf=0;mf<2;mf++)
        #pragma unroll
        for (int nf=0;nf<4;nf++)
            #pragma unroll
            for (int r=0;r<4;r++) acc[mf][nf][r] = 0.f;

    mma_core<64>(g_w4h + 3*(size_t)C_*C_ + (size_t)m0*C_, g_w4l + 3*(size_t)C_*C_ + (size_t)m0*C_,
                 g_hvTh + ((size_t)b*N_ + n0)*C_,         g_hvTl + ((size_t)b*N_ + n0)*C_,
                 C_, C_, sb, acc);

    const int tid = threadIdx.x, lane = tid & 31, wid = tid >> 5;
    const int wm = (wid & 3) * 32, wn = (wid >> 2) * 32;
    const int gid = lane >> 2, tig = lane & 3;
    #pragma unroll
    for (int mf=0;mf<2;mf++)
        #pragma unroll
        for (int nf=0;nf<4;nf++)
            #pragma unroll
            for (int h=0;h<2;h++){
                int m = m0 + wm + mf*16 + gid + h*8;
                int n = n0 + wn + nf*8 + tig*2;
                size_t off = (size_t)b*CN + (size_t)m*N_ + n;
                float bm = bp[m];
                float2 st;
                st.x = acc[mf][nf][h*2]   + bm + x[off];
                st.y = acc[mf][nf][h*2+1] + bm + x[off+1];
                *(float2*)&out[off] = st;
            }
}

// ---------------- host launch ----------------
extern "C" void kernel_launch(void* const* d_in, const int* in_sizes, int n_in,
                              void* d_out, int out_size){
    const float* x    = (const float*)d_in[0];
    const float* gma  = (const float*)d_in[1];
    const float* bta  = (const float*)d_in[2];
    const float* wq   = (const float*)d_in[3];
    const float* bq   = (const float*)d_in[4];
    const float* wk   = (const float*)d_in[5];
    const float* bk   = (const float*)d_in[6];
    const float* wv   = (const float*)d_in[7];
    const float* bv   = (const float*)d_in[8];
    const float* wp   = (const float*)d_in[9];
    const float* bp   = (const float*)d_in[10];
    float* out   = (float*)d_out;
    float* w_out = out + (size_t)B_*CN;

    cudaFuncSetAttribute(qk_mma,     cudaFuncAttributeMaxDynamicSharedMemorySize, SMEM_SC);
    cudaFuncSetAttribute(v_mma,      cudaFuncAttributeMaxDynamicSharedMemorySize, SMEM_SC);
    cudaFuncSetAttribute(scores_mma, cudaFuncAttributeMaxDynamicSharedMemorySize, SMEM_SC);
    cudaFuncSetAttribute(pv_mma,     cudaFuncAttributeMaxDynamicSharedMemorySize, SMEM_SC);
    cudaFuncSetAttribute(proj_mma,   cudaFuncAttributeMaxDynamicSharedMemorySize, SMEM_SC);

    conv_w4<<<512, 256>>>(wq, wk, wv, wp);
    gn_kernel<<<64, 256>>>(x, gma, bta);

    // q, k (512 CTAs) and v (256 CTAs), all 2 CTAs/SM
    qk_mma<<<dim3(4,32,4), 256, SMEM_SC>>>(bq, bk);
    v_mma<<<dim3(64,2,2), 256, SMEM_SC>>>(bv);

    // e = exp(qk/16) -> bf16 hi/lo (i,m) + deterministic partials (full 3-term)
    scores_mma<<<dim3(64,32,2), 256, SMEM_SC>>>();
    rowsum_inv<<<32, 256>>>();

    // w_out[b][m][i] = (eh+el)*rinv (transposing normalize)
    norm_t<<<dim3(64,64,2), 256>>>(w_out);

    // hvT (b, n, c) bf16 hi/lo
    pv_mma<<<dim3(64,2,2), 256, SMEM_SC>>>();

    // out = x + wp*hv + bp
    proj_mma<<<dim3(64,2,2), 256, SMEM_SC>>>(out, x, bp);
}

// round 17
// speedup vs baseline: 1.4600x; 1.0087x over previous
#include <cuda_runtime.h>
#include <cuda_bf16.h>
#include <cstdint>
#include <cstddef>

#define B_ 2
#define C_ 256
#define N_ 4096
#define CN (C_*N_)

// ---------------- scratch (static __device__, no allocation) ----------------
__device__ float g_partial[B_*N_*64];  // per (b,i,mtile64) partial exp-sums
__device__ float g_rinv[B_*N_];        // 1/rowsum

// bf16 hi/lo split operands
__device__ __nv_bfloat16 g_hnTh[B_*N_*C_], g_hnTl[B_*N_*C_]; // hn^T (b, n, c)
__device__ __nv_bfloat16 g_w4h[4*C_*C_],   g_w4l[4*C_*C_];   // wq, wk, wv, wp (o, c)
__device__ __nv_bfloat16 g_qTh[B_*N_*C_],  g_qTl[B_*N_*C_];  // qT (b, n, c)
__device__ __nv_bfloat16 g_kTh[B_*N_*C_],  g_kTl[B_*N_*C_];  // kT (b, n, c)
__device__ __nv_bfloat16 g_vh [B_*CN],     g_vl [B_*CN];     // v  (b, c, n)
__device__ __nv_bfloat16 g_hvTh[B_*N_*C_], g_hvTl[B_*N_*C_]; // hv^T (b, n, c)
__device__ __nv_bfloat16 g_eh [(size_t)B_*N_*N_];            // e (b, i, m) hi
__device__ __nv_bfloat16 g_el [(size_t)B_*N_*N_];            // e (b, i, m) lo

// ---------------- helpers ----------------
__device__ __forceinline__ uint32_t smem_u32(const void* p){
    uint32_t a;
    asm("{ .reg .u64 t; cvta.to.shared.u64 t, %1; cvt.u32.u64 %0, t; }" : "=r"(a) : "l"(p));
    return a;
}
__device__ __forceinline__ uint32_t sw128(uint32_t o){ return o ^ ((o >> 3) & 0x70); }

__device__ __forceinline__ void ldsm4(uint32_t r[4], uint32_t addr){
    asm volatile("ldmatrix.sync.aligned.m8n8.x4.shared.b16 {%0,%1,%2,%3}, [%4];"
        : "=r"(r[0]), "=r"(r[1]), "=r"(r[2]), "=r"(r[3]) : "r"(addr));
}
__device__ __forceinline__ void mma16816(float d[4], const uint32_t a[4], uint32_t b0, uint32_t b1){
    asm volatile("mma.sync.aligned.m16n8k16.row.col.f32.bf16.bf16.f32 "
        "{%0,%1,%2,%3}, {%4,%5,%6,%7}, {%8,%9}, {%0,%1,%2,%3};"
        : "+f"(d[0]), "+f"(d[1]), "+f"(d[2]), "+f"(d[3])
        : "r"(a[0]), "r"(a[1]), "r"(a[2]), "r"(a[3]), "r"(b0), "r"(b1));
}
__device__ __forceinline__ void cpa16(uint32_t dst, const void* src){
    asm volatile("cp.async.cg.shared.global [%0], [%1], 16;"
        :: "r"(dst), "l"(__cvta_generic_to_global(src)) : "memory");
}
#define CP_COMMIT() asm volatile("cp.async.commit_group;" ::: "memory")
#define CP_WAIT0()  asm volatile("cp.async.wait_group 0;" ::: "memory")

__device__ __forceinline__ void bfsplit2(float v0, float v1, uint32_t& hi, uint32_t& lo){
    __nv_bfloat16 h0 = __float2bfloat16(v0);
    __nv_bfloat16 h1 = __float2bfloat16(v1);
    __nv_bfloat16 l0 = __float2bfloat16(v0 - __bfloat162float(h0));
    __nv_bfloat16 l1 = __float2bfloat16(v1 - __bfloat162float(h1));
    hi = (uint32_t)__bfloat16_as_ushort(h0) | ((uint32_t)__bfloat16_as_ushort(h1) << 16);
    lo = (uint32_t)__bfloat16_as_ushort(l0) | ((uint32_t)__bfloat16_as_ushort(l1) << 16);
}

// ---------------- templated 128xBN mma core (full 3-term bf16 hi/lo) ----------------
// A: 128 rows k-major (hi+lo); B: BN rows k-major (hi+lo).
// Terms per k16: ah*bh + ah*bl + al*bh. Stage: AH@0, AL@16K, BH@32K, BL@32K+BN*128.
// 2-stage pipeline, ONE __syncthreads per chunk:
//   wait(group c) -> sync (also proves compute(c-1) done) -> issue load(c+1) -> compute(c)
template<int BN>
__device__ __forceinline__ void mc_load(
    const __nv_bfloat16* __restrict__ Ah, const __nv_bfloat16* __restrict__ Al,
    const __nv_bfloat16* __restrict__ Bh, const __nv_bfloat16* __restrict__ Bl,
    int stride, int kk, uint32_t sbuf)
{
    constexpr int BH_OFF = 32768;
    constexpr int BL_OFF = BH_OFF + BN*128;
    const int tid = threadIdx.x;
    #pragma unroll
    for (int t = 0; t < 4; t++){
        int idx = tid + t*256;
        int r = idx >> 3, c16 = idx & 7;
        uint32_t so = sw128((uint32_t)(r*128 + c16*16));
        size_t go = (size_t)r*stride + kk + c16*8;
        cpa16(sbuf + so, Ah + go);
        cpa16(sbuf + 16384 + so, Al + go);
    }
    #pragma unroll
    for (int t = 0; t < BN/32; t++){
        int idx = tid + t*256;
        int r = idx >> 3, c16 = idx & 7;
        uint32_t so = sw128((uint32_t)(r*128 + c16*16));
        size_t go = (size_t)r*stride + kk + c16*8;
        cpa16(sbuf + BH_OFF + so, Bh + go);
        cpa16(sbuf + BL_OFF + so, Bl + go);
    }
}

template<int BN>
__device__ __forceinline__ void mc_compute(uint32_t sbuf, float acc[2][BN/16][4])
{
    constexpr int BH_OFF = 32768;
    constexpr int BL_OFF = BH_OFF + BN*128;
    const int tid  = threadIdx.x;
    const int lane = tid & 31, wid = tid >> 5;
    const int wm = (wid & 3) * 32, wn = (wid >> 2) * (BN/2);
    const int lrow = ((lane >> 3) & 1) * 8 + (lane & 7);
    const int lk   = (lane >> 4) * 8;
    #pragma unroll
    for (int k16 = 0; k16 < 4; k16++){
        uint32_t ah[2][4], al[2][4];
        #pragma unroll
        for (int mf = 0; mf < 2; mf++){
            uint32_t off = sw128((uint32_t)((wm + mf*16 + lrow)*128 + (k16*16 + lk)*2));
            ldsm4(ah[mf], sbuf + off);
            ldsm4(al[mf], sbuf + 16384 + off);
        }
        #pragma unroll
        for (int nf2 = 0; nf2 < BN/32; nf2++){
            uint32_t boff = sw128((uint32_t)((wn + nf2*16 + lrow)*128 + (k16*16 + lk)*2));
            uint32_t bh[4], bl[4];
            ldsm4(bh, sbuf + BH_OFF + boff);
            ldsm4(bl, sbuf + BL_OFF + boff);
            #pragma unroll
            for (int mf = 0; mf < 2; mf++){
                #pragma unroll
                for (int w = 0; w < 2; w++){
                    int nf = nf2*2 + w;
                    mma16816(acc[mf][nf], ah[mf], bh[w], bh[w+2]);
                    mma16816(acc[mf][nf], ah[mf], bl[w], bl[w+2]);
                    mma16816(acc[mf][nf], al[mf], bh[w], bh[w+2]);
                }
            }
        }
    }
}

template<int BN>
__device__ __forceinline__ void mma_core(
    const __nv_bfloat16* __restrict__ Ah, const __nv_bfloat16* __restrict__ Al,
    const __nv_bfloat16* __restrict__ Bh, const __nv_bfloat16* __restrict__ Bl,
    int stride, int K, uint32_t sb, float acc[2][BN/16][4])
{
    constexpr int STAGE = 32768 + BN*256;
    const int nch = K >> 6;
    mc_load<BN>(Ah, Al, Bh, Bl, stride, 0, sb);
    CP_COMMIT();
    for (int c = 0; c < nch; c++){
        CP_WAIT0();          // group c complete (c+1 not yet issued by this thread)
        __syncthreads();     // data c visible everywhere; everyone finished compute(c-1)
        if (c + 1 < nch){
            mc_load<BN>(Ah, Al, Bh, Bl, stride, (c+1)*64, sb + ((c+1)&1)*STAGE);
            CP_COMMIT();
        }
        mc_compute<BN>(sb + (c&1)*STAGE, acc);
    }
    __syncthreads();         // epilogue may reuse smem
}

#define SMEM_SC (2*49152)      // BN=64: 48KB/stage -> 96KB/CTA -> 2 CTAs/SM

// ---------------- wq/wk/wv/wp -> bf16 hi/lo (layout unchanged: (o, c) k-major) ----------------
__global__ void conv_w4(const float* __restrict__ wq, const float* __restrict__ wk,
                        const float* __restrict__ wv, const float* __restrict__ wp){
    int idx = blockIdx.x*256 + threadIdx.x;       // 0 .. 4*32768-1 (pairs)
    int which = idx >> 15;
    int pair  = idx & 32767;
    const float* src = (which==0)?wq:(which==1)?wk:(which==2)?wv:wp;
    float v0 = src[pair*2], v1 = src[pair*2+1];
    uint32_t hi, lo;
    bfsplit2(v0, v1, hi, lo);
    *(uint32_t*)&g_w4h[(size_t)which*C_*C_ + pair*2] = hi;
    *(uint32_t*)&g_w4l[(size_t)which*C_*C_ + pair*2] = lo;
}

// ---------------- GroupNorm -> hn^T (b, n, c) bf16 hi/lo ----------------
__global__ void gn_kernel(const float* __restrict__ x, const float* __restrict__ gma,
                          const float* __restrict__ bta){
    const int bg = blockIdx.x;                 // 64 = b*32 + grp
    const int b = bg >> 5, grp = bg & 31;
    const size_t base = (size_t)b*CN + (size_t)grp*8*N_;
    const float* xp = x + base;
    const int tid = threadIdx.x;
    float s = 0.f, sq = 0.f;
    for (int i = tid; i < 8*N_; i += 256){ float v = xp[i]; s += v; sq += v*v; }
    __shared__ float ss[256], sk[256];
    ss[tid]=s; sk[tid]=sq; __syncthreads();
    for (int o=128;o>0;o>>=1){
        if (tid < o){ ss[tid]+=ss[tid+o]; sk[tid]+=sk[tid+o]; }
        __syncthreads();
    }
    const float inv = 1.0f/(8.0f*N_);
    float mu = ss[0]*inv;
    float var = sk[0]*inv - mu*mu;
    float rs = rsqrtf(var + 1e-6f);
    float gm[8], bt[8];
    #pragma unroll
    for (int ch=0; ch<8; ch++){ gm[ch] = gma[grp*8+ch]*rs; bt[ch] = bta[grp*8+ch]; }
    for (int n = tid; n < N_; n += 256){
        uint32_t hi[4], lo[4];
        #pragma unroll
        for (int p=0; p<4; p++){
            float v0 = (xp[(size_t)(p*2  )*N_ + n] - mu)*gm[p*2]   + bt[p*2];
            float v1 = (xp[(size_t)(p*2+1)*N_ + n] - mu)*gm[p*2+1] + bt[p*2+1];
            bfsplit2(v0, v1, hi[p], lo[p]);
        }
        size_t off = ((size_t)b*N_ + n)*C_ + grp*8;
        *(uint4*)&g_hnTh[off] = *(uint4*)hi;
        *(uint4*)&g_hnTl[off] = *(uint4*)lo;
    }
}

// ---------------- merged QKV: 768 CTAs, linear decode ----------------
// blk <  512: q/k.  z=blk>>7 (which*2+b), rem=blk&127: m0=(rem>>2)*128 (n rows), n0=(rem&3)*64 (o cols)
//   qT[n][o] = sum_c hnT[n][c] w[o][c] + b[o]
// blk >= 512: v.  vblk=blk-512: b=vblk>>7, rem=vblk&127: m0=(rem>>6)*128 (o rows), n0=(rem&63)*64 (n cols)
//   v[o][n] = sum_c wv[o][c] hnT[n][c] + b[o]
__global__ void __launch_bounds__(256,2) qkv_mma(
    const float* __restrict__ bq, const float* __restrict__ bk, const float* __restrict__ bv)
{
    extern __shared__ char smem[];
    uint32_t sb = smem_u32(smem);
    const int blk = blockIdx.x;
    const __nv_bfloat16 *Ah, *Al, *Bh, *Bl;
    int m0, n0, which, b;
    if (blk < 512){
        int z = blk >> 7, rem = blk & 127;
        which = z >> 1; b = z & 1;
        m0 = (rem >> 2) * 128;  n0 = (rem & 3) * 64;
        Ah = g_hnTh + ((size_t)b*N_ + m0)*C_;  Al = g_hnTl + ((size_t)b*N_ + m0)*C_;
        Bh = g_w4h + (size_t)which*C_*C_ + (size_t)n0*C_;
        Bl = g_w4l + (size_t)which*C_*C_ + (size_t)n0*C_;
    } else {
        int vblk = blk - 512, rem = vblk & 127;
        which = 2; b = vblk >> 7;
        m0 = (rem >> 6) * 128;  n0 = (rem & 63) * 64;
        Ah = g_w4h + 2*(size_t)C_*C_ + (size_t)m0*C_;
        Al = g_w4l + 2*(size_t)C_*C_ + (size_t)m0*C_;
        Bh = g_hnTh + ((size_t)b*N_ + n0)*C_;  Bl = g_hnTl + ((size_t)b*N_ + n0)*C_;
    }

    float acc[2][4][4];
    #pragma unroll
    for (int mf=0;mf<2;mf++)
        #pragma unroll
        for (int nf=0;nf<4;nf++)
            #pragma unroll
            for (int r=0;r<4;r++) acc[mf][nf][r] = 0.f;

    mma_core<64>(Ah, Al, Bh, Bl, C_, C_, sb, acc);

    const int tid = threadIdx.x, lane = tid & 31, wid = tid >> 5;
    const int wm = (wid & 3) * 32, wn = (wid >> 2) * 32;
    const int gid = lane >> 2, tig = lane & 3;
    const float* bias = (which==0)?bq:(which==1)?bk:bv;
    #pragma unroll
    for (int mf=0;mf<2;mf++)
        #pragma unroll
        for (int nf=0;nf<4;nf++)
            #pragma unroll
            for (int h=0;h<2;h++){
                int m = m0 + wm + mf*16 + gid + h*8;
                int n = n0 + wn + nf*8 + tig*2;
                float v0 = acc[mf][nf][h*2], v1 = acc[mf][nf][h*2+1];
                uint32_t hi, lo;
                if (which < 2){
                    v0 += bias[n]; v1 += bias[n+1];
                    bfsplit2(v0, v1, hi, lo);
                    size_t off = ((size_t)b*N_ + m)*C_ + n;
                    if (which == 0){ *(uint32_t*)&g_qTh[off] = hi; *(uint32_t*)&g_qTl[off] = lo; }
                    else           { *(uint32_t*)&g_kTh[off] = hi; *(uint32_t*)&g_kTl[off] = lo; }
                } else {
                    float bm = bias[m]; v0 += bm; v1 += bm;
                    bfsplit2(v0, v1, hi, lo);
                    size_t off = (size_t)b*CN + (size_t)m*N_ + n;
                    *(uint32_t*)&g_vh[off] = hi; *(uint32_t*)&g_vl[off] = lo;
                }
            }
}

// ---------------- scores: e = exp(q.k^T / 16) -> eh/el (i,m) + partial sums ----------------
// FULL 3-term; 128(i) x 64(m) tiles -> 2 CTAs/SM.
// grid: x = m-tile (64), y = i-tile (32), z = b; 256 threads
__global__ void __launch_bounds__(256,2) scores_mma()
{
    extern __shared__ char smem[];
    uint32_t sb = smem_u32(smem);
    const int tid = threadIdx.x;
    const int b  = blockIdx.z;
    const int m0 = blockIdx.x*64;
    const int i0 = blockIdx.y*128;

    float acc[2][4][4];
    #pragma unroll
    for (int mf=0;mf<2;mf++)
        #pragma unroll
        for (int nf=0;nf<4;nf++)
            #pragma unroll
            for (int r=0;r<4;r++) acc[mf][nf][r] = 0.f;

    mma_core<64>(g_qTh + ((size_t)b*N_ + i0)*C_, g_qTl + ((size_t)b*N_ + i0)*C_,
                 g_kTh + ((size_t)b*N_ + m0)*C_, g_kTl + ((size_t)b*N_ + m0)*C_,
                 C_, C_, sb, acc);

    // exp into smT[i_local 128][m_local 64] (pitch 65)
    float* smT = (float*)smem;
    const int lane = tid & 31, wid = tid >> 5;
    const int wm = (wid & 3) * 32, wn = (wid >> 2) * 32;
    const int gid = lane >> 2, tig = lane & 3;
    #pragma unroll
    for (int mf=0;mf<2;mf++)
        #pragma unroll
        for (int nf=0;nf<4;nf++)
            #pragma unroll
            for (int h=0;h<2;h++){
                int il = wm + mf*16 + gid + h*8;
                int ml = wn + nf*8 + tig*2;
                smT[il*65 + ml]     = __expf(acc[mf][nf][h*2]   * 0.0625f);
                smT[il*65 + ml + 1] = __expf(acc[mf][nf][h*2+1] * 0.0625f);
            }
    __syncthreads();

    // e bf16 hi/lo in (i, m), coalesced: 128 rows x 2 halves of 32
    {
        int il = tid >> 1, half = tid & 1;
        const float* row = smT + il*65 + half*32;
        size_t go = ((size_t)b*N_ + i0 + il)*N_ + m0 + half*32;
        #pragma unroll
        for (int cb=0; cb<32; cb+=8){
            uint32_t hb[4], lb[4];
            #pragma unroll
            for (int q=0;q<4;q++)
                bfsplit2(row[cb+q*2], row[cb+q*2+1], hb[q], lb[q]);
            *(uint4*)&g_eh[go + cb] = *(uint4*)hb;
            *(uint4*)&g_el[go + cb] = *(uint4*)lb;
        }
    }

    // deterministic partial row sums over this 64-wide m-tile
    if (tid < 128){
        float s = 0.f;
        #pragma unroll 8
        for (int m=0;m<64;m++) s += smT[tid*65 + m];
        g_partial[((size_t)b*N_ + i0 + tid)*64 + blockIdx.x] = s;
    }
}

// ---------------- reduce partials -> reciprocal row sums ----------------
__global__ void rowsum_inv(){
    int idx = blockIdx.x*256 + threadIdx.x;
    float s = 0.f;
    #pragma unroll
    for (int t=0;t<64;t++) s += g_partial[(size_t)idx*64 + t];
    g_rinv[idx] = 1.0f/s;
}

// ---------------- w_out[b][m][i] = (eh+el)[b][i][m] * rinv[b][i]  (tiled transpose) ----------------
__global__ void __launch_bounds__(256) norm_t(float* __restrict__ w_out){
    __shared__ float t[64][65];
    const int b = blockIdx.z, m0 = blockIdx.x*64, i0 = blockIdx.y*64;
    const int tid = threadIdx.x;
    const __nv_bfloat16* eh = g_eh + ((size_t)b*N_ + i0)*N_ + m0;
    const __nv_bfloat16* el = g_el + ((size_t)b*N_ + i0)*N_ + m0;
    const int r = tid >> 2, cc = tid & 3;
    const float rv = g_rinv[(size_t)b*N_ + i0 + r];
    #pragma unroll
    for (int it=0; it<2; it++){
        int c8 = cc + it*4;
        uint4 hv4 = *(const uint4*)(eh + (size_t)r*N_ + c8*8);
        uint4 lv4 = *(const uint4*)(el + (size_t)r*N_ + c8*8);
        const __nv_bfloat16* hp = (const __nv_bfloat16*)&hv4;
        const __nv_bfloat16* lp = (const __nv_bfloat16*)&lv4;
        #pragma unroll
        for (int j=0;j<8;j++)
            t[r][c8*8+j] = (__bfloat162float(hp[j]) + __bfloat162float(lp[j])) * rv;
    }
    __syncthreads();
    const int mr = tid >> 2, ic = tid & 3;
    float* wrow = w_out + (size_t)b*N_*N_ + (size_t)(m0+mr)*N_ + i0;
    #pragma unroll
    for (int it=0; it<4; it++){
        int i4 = ic + it*4;
        float4 o;
        o.x = t[i4*4+0][mr]; o.y = t[i4*4+1][mr];
        o.z = t[i4*4+2][mr]; o.w = t[i4*4+3][mr];
        *(float4*)(wrow + i4*4) = o;
    }
}

// ---------------- PV: hvT[i][c] = (sum_m v[c][m] e[i][m]) * rinv[i], bf16 hi/lo ----------------
// 128(c) x 64(i) tiles -> 2 CTAs/SM; grid (64, 2, 2); 256 threads
__global__ void __launch_bounds__(256,2) pv_mma()
{
    extern __shared__ char smem[];
    uint32_t sb = smem_u32(smem);
    const int tid = threadIdx.x;
    const int b  = blockIdx.z;
    const int c0 = blockIdx.y*128;
    const int i0 = blockIdx.x*64;

    float acc[2][4][4];
    #pragma unroll
    for (int mf=0;mf<2;mf++)
        #pragma unroll
        for (int nf=0;nf<4;nf++)
            #pragma unroll
            for (int r=0;r<4;r++) acc[mf][nf][r] = 0.f;

    mma_core<64>(g_vh + (size_t)b*CN + (size_t)c0*N_, g_vl + (size_t)b*CN + (size_t)c0*N_,
                 g_eh + ((size_t)b*N_ + i0)*N_,       g_el + ((size_t)b*N_ + i0)*N_,
                 N_, N_, sb, acc);

    // stage (i, c) f32 with rinv applied, then write hvT (i, c) hi/lo coalesced
    float* smT = (float*)smem;                 // [i_local 64][pitch 129]
    const float* rinv = g_rinv + (size_t)b*N_ + i0;
    const int lane = tid & 31, wid = tid >> 5;
    const int wm = (wid & 3) * 32, wn = (wid >> 2) * 32;
    const int gid = lane >> 2, tig = lane & 3;
    #pragma unroll
    for (int mf=0;mf<2;mf++)
        #pragma unroll
        for (int nf=0;nf<4;nf++)
            #pragma unroll
            for (int h=0;h<2;h++){
                int c = wm + mf*16 + gid + h*8;
                int n = wn + nf*8 + tig*2;
                smT[n*129 + c]     = acc[mf][nf][h*2]   * rinv[n];
                smT[(n+1)*129 + c] = acc[mf][nf][h*2+1] * rinv[n+1];
            }
    __syncthreads();
    {
        int il = tid >> 2, qq = tid & 3;       // 64 rows x 4 quarters of 32 c
        const float* row = smT + il*129 + qq*32;
        size_t go = ((size_t)b*N_ + i0 + il)*C_ + c0 + qq*32;
        #pragma unroll
        for (int cb=0; cb<32; cb+=8){
            uint32_t hb[4], lb[4];
            #pragma unroll
            for (int q=0;q<4;q++)
                bfsplit2(row[cb+q*2], row[cb+q*2+1], hb[q], lb[q]);
            *(uint4*)&g_hvTh[go + cb] = *(uint4*)hb;
            *(uint4*)&g_hvTl[go + cb] = *(uint4*)lb;
        }
    }
}

// ---------------- proj: out[b][o][n] = x + sum_c wp[o][c] hvT[n][c] + bp[o] ----------------
// BN=64, 2 CTAs/SM; grid: x = n-tile (64), y = o-tile (2), z = b
__global__ void __launch_bounds__(256,2) proj_mma(
    float* __restrict__ out, const float* __restrict__ x, const float* __restrict__ bp)
{
    extern __shared__ char smem[];
    uint32_t sb = smem_u32(smem);
    const int b  = blockIdx.z;
    const int m0 = blockIdx.y*128;     // o
    const int n0 = blockIdx.x*64;      // n

    float acc[2][4][4];
    #pragma unroll
    for (int mf=0;mf<2;mf++)
        #pragma unroll
        for (int nf=0;nf<4;nf++)
            #pragma unroll
            for (int r=0;r<4;r++) acc[mf][nf][r] = 0.f;

    mma_core<64>(g_w4h + 3*(size_t)C_*C_ + (size_t)m0*C_, g_w4l + 3*(size_t)C_*C_ + (size_t)m0*C_,
                 g_hvTh + ((size_t)b*N_ + n0)*C_,         g_hvTl + ((size_t)b*N_ + n0)*C_,
                 C_, C_, sb, acc);

    const int tid = threadIdx.x, lane = tid & 31, wid = tid >> 5;
    const int wm = (wid & 3) * 32, wn = (wid >> 2) * 32;
    const int gid = lane >> 2, tig = lane & 3;
    #pragma unroll
    for (int mf=0;mf<2;mf++)
        #pragma unroll
        for (int nf=0;nf<4;nf++)
            #pragma unroll
            for (int h=0;h<2;h++){
                int m = m0 + wm + mf*16 + gid + h*8;
                int n = n0 + wn + nf*8 + tig*2;
                size_t off = (size_t)b*CN + (size_t)m*N_ + n;
                float bm = bp[m];
                float2 st;
                st.x = acc[mf][nf][h*2]   + bm + x[off];
                st.y = acc[mf][nf][h*2+1] + bm + x[off+1];
                *(float2*)&out[off] = st;
            }
}

// ---------------- host launch ----------------
extern "C" void kernel_launch(void* const* d_in, const int* in_sizes, int n_in,
                              void* d_out, int out_size){
    const float* x    = (const float*)d_in[0];
    const float* gma  = (const float*)d_in[1];
    const float* bta  = (const float*)d_in[2];
    const float* wq   = (const float*)d_in[3];
    const float* bq   = (const float*)d_in[4];
    const float* wk   = (const float*)d_in[5];
    const float* bk   = (const float*)d_in[6];
    const float* wv   = (const float*)d_in[7];
    const float* bv   = (const float*)d_in[8];
    const float* wp   = (const float*)d_in[9];
    const float* bp   = (const float*)d_in[10];
    float* out   = (float*)d_out;
    float* w_out = out + (size_t)B_*CN;

    cudaFuncSetAttribute(qkv_mma,    cudaFuncAttributeMaxDynamicSharedMemorySize, SMEM_SC);
    cudaFuncSetAttribute(scores_mma, cudaFuncAttributeMaxDynamicSharedMemorySize, SMEM_SC);
    cudaFuncSetAttribute(pv_mma,     cudaFuncAttributeMaxDynamicSharedMemorySize, SMEM_SC);
    cudaFuncSetAttribute(proj_mma,   cudaFuncAttributeMaxDynamicSharedMemorySize, SMEM_SC);

    conv_w4<<<512, 256>>>(wq, wk, wv, wp);
    gn_kernel<<<64, 256>>>(x, gma, bta);

    // q, k, v in one 768-CTA launch, 2 CTAs/SM
    qkv_mma<<<768, 256, SMEM_SC>>>(bq, bk, bv);

    // e = exp(qk/16) -> bf16 hi/lo (i,m) + deterministic partials (full 3-term)
    scores_mma<<<dim3(64,32,2), 256, SMEM_SC>>>();
    rowsum_inv<<<32, 256>>>();

    // w_out[b][m][i] = (eh+el)*rinv (transposing normalize)
    norm_t<<<dim3(64,64,2), 256>>>(w_out);

    // hvT (b, n, c) bf16 hi/lo
    pv_mma<<<dim3(64,2,2), 256, SMEM_SC>>>();

    // out = x + wp*hv + bp
    proj_mma<<<dim3(64,2,2), 256, SMEM_SC>>>(out, x, bp);
}